// round 17
// baseline (speedup 1.0000x reference)
#include <cuda_runtime.h>
#include <math.h>

#define B_   16
#define T_   128
#define I_   256
#define H_   256
#define NZ_  1024          // 4*H
#define NBLK 128           // rec blocks: 8 groups x 16
#define GRPB 16            // rec arrivals per (group,step)

typedef unsigned long long ull;

// Scratch (static device globals: no allocation)
__device__ float    g_xz[T_ * NZ_ * B_];   // [t][n][b]  8 MB
__device__ float    g_h[2][B_ * H_];       // ping-pong hidden state [b][u]
__device__ unsigned g_arr[8 * T_ * 32];    // per-(group,step) counters, 128B apart

// fast transcendentals: ex2.approx + rcp.approx (~1e-6 rel err each)
__device__ __forceinline__ float fsigmoid(float x) {
    float e; asm("ex2.approx.ftz.f32 %0, %1;" : "=f"(e) : "f"(-1.4426950408889634f * x));
    float r; asm("rcp.approx.ftz.f32 %0, %1;" : "=f"(r) : "f"(1.0f + e));
    return r;
}
__device__ __forceinline__ float ftanh_(float x) {
    x = fminf(fmaxf(x, -30.0f), 30.0f);
    float e; asm("ex2.approx.ftz.f32 %0, %1;" : "=f"(e) : "f"(2.8853900817779268f * x));
    float r; asm("rcp.approx.ftz.f32 %0, %1;" : "=f"(r) : "f"(e + 1.0f));
    return (e - 1.0f) * r;
}

// packed f32x2 helpers (sm_100+)
__device__ __forceinline__ ull pack2(float lo, float hi) {
    ull r; asm("mov.b64 %0, {%1,%2};" : "=l"(r) : "f"(lo), "f"(hi)); return r;
}
__device__ __forceinline__ void unpack2(ull v, float& lo, float& hi) {
    asm("mov.b64 {%0,%1}, %2;" : "=f"(lo), "=f"(hi) : "l"(v));
}
__device__ __forceinline__ ull fma2(ull a, ull b, ull c) {
    ull d; asm("fma.rn.f32x2 %0, %1, %2, %3;" : "=l"(d) : "l"(a), "l"(b), "l"(c));
    return d;
}
__device__ __forceinline__ unsigned acq_load(const unsigned* p) {
    unsigned v;
    asm volatile("ld.acquire.gpu.global.u32 %0, [%1];" : "=r"(v) : "l"(p) : "memory");
    return v;
}

// ---------------------------------------------------------------------------
// Kernel 1: XZ[t][n][b] = sum_k x[b][t][k] * Wih[k][n]   (k < 256 rows of Wih)
// grid (8 n-blocks, 64 t-pairs), 256 threads, 2 timesteps share each W panel.
// Also resets the rec counters (graph-replay safe: stream-ordered first).
// ---------------------------------------------------------------------------
__global__ void __launch_bounds__(256)
xz_kernel(const float* __restrict__ x, const float* __restrict__ Wih)
{
    if (blockIdx.y == 0) {
        // 8 blocks x 256 threads zero 32768 counters (16 each)
        int base = (blockIdx.x * 256 + threadIdx.x) * 16;
        #pragma unroll
        for (int i = 0; i < 16; i++) g_arr[base + i] = 0u;
    }

    __shared__ float x_s[2][I_ * B_];   // [half][k][b], 32 KB
    __shared__ float w_s[16 * 128];     // shared 16-row k-panel, 8 KB

    const int tid  = threadIdx.x;
    const int half = tid >> 7;          // 0/1 -> t0/t1
    const int htid = tid & 127;
    const int n0   = blockIdx.x * 128;
    const int t    = blockIdx.y * 2 + half;

    for (int idx = htid; idx < B_ * I_; idx += 128) {
        int b = idx >> 8;
        int k = idx & 255;
        x_s[half][k * B_ + b] = x[(b * T_ + t) * I_ + k];
    }

    const int bq = htid >> 5;
    const int ng = htid & 31;
    const int b0 = bq * 4;
    const int nn = ng * 4;

    float acc[4][4];
    #pragma unroll
    for (int i = 0; i < 4; i++)
        #pragma unroll
        for (int j = 0; j < 4; j++) acc[i][j] = 0.f;

    for (int kb = 0; kb < 16; kb++) {
        __syncthreads();
        for (int q = tid; q < 512; q += 256) {
            int r  = q >> 5;
            int c4 = q & 31;
            ((float4*)w_s)[q] =
                ((const float4*)(Wih + (size_t)(kb * 16 + r) * NZ_ + n0))[c4];
        }
        __syncthreads();
        #pragma unroll
        for (int kk = 0; kk < 16; kk++) {
            float4 xv = *(const float4*)&x_s[half][(kb * 16 + kk) * B_ + b0];
            float4 wv = *(const float4*)&w_s[kk * 128 + nn];
            float xr[4] = {xv.x, xv.y, xv.z, xv.w};
            float wr_[4] = {wv.x, wv.y, wv.z, wv.w};
            #pragma unroll
            for (int i = 0; i < 4; i++)
                #pragma unroll
                for (int j = 0; j < 4; j++)
                    acc[i][j] += xr[i] * wr_[j];
        }
    }

    #pragma unroll
    for (int j = 0; j < 4; j++) {
        float4 o = make_float4(acc[0][j], acc[1][j], acc[2][j], acc[3][j]);
        *(float4*)&g_xz[(size_t)(t * NZ_ + n0 + nn + j) * B_ + b0] = o;
    }
}

// ---------------------------------------------------------------------------
// Kernel 2: persistent recurrence — 8 independent groups of 16 blocks.
// Group g owns batches {2g, 2g+1}; block r owns units 16r..16r+15.
// 512 threads/block, warp = unit (weights 32 ull/lane, fits 128-reg cap).
// Per-warp polling (lane0 of each warp), 2 syncthreads per step.
// ---------------------------------------------------------------------------
__global__ void __launch_bounds__(512)
rec_kernel(const float* __restrict__ h_init, const float* __restrict__ c_init,
           const float* __restrict__ out0,
           const float* __restrict__ Wih,  const float* __restrict__ Whh,
           const float* __restrict__ b_ih, const float* __restrict__ b_hh,
           float* __restrict__ dout)
{
    __shared__ float h_s[2 * H_];           // 2 KB: the group's 2 batches
    __shared__ float d_s[16][2][4][2];      // [unit][mat][gate][batch]
    __shared__ float A_s[16][4][2];         // running atten@Wa
    __shared__ float c_s[16][2];
    __shared__ float att_s[16][2];
    __shared__ float bias_s[16][4];

    const int tid  = threadIdx.x;
    const int bid  = blockIdx.x;
    const int g    = bid >> 4;     // group 0..7 -> batches 2g, 2g+1
    const int r    = bid & 15;     // unit block -> units 16r..16r+15
    const int u0   = r * 16;
    const int b0   = g * 2;
    const int w    = tid >> 5;     // warp = local unit lu (0..15)
    const int lane = tid & 31;
    const int cs   = lane >> 4;    // 0 -> Whh, 1 -> Wa (Wih rows 256..511)
    const int kc   = lane & 15;    // k-pair base = 32*j + 2*kc

    // packed weight slice in registers: wr2[c][j] = {W[k0][n], W[k0+1][n]}
    ull wr2[4][8];                 // 32 ull = 64 regs
    #pragma unroll
    for (int c = 0; c < 4; c++) {
        const int n = u0 + w + 256 * c;
        #pragma unroll
        for (int j = 0; j < 8; j++) {
            const int k0 = 32 * j + 2 * kc;
            float w0 = cs ? Wih[(size_t)(256 + k0) * NZ_ + n]
                          : Whh[(size_t)k0 * NZ_ + n];
            float w1 = cs ? Wih[(size_t)(256 + k0 + 1) * NZ_ + n]
                          : Whh[(size_t)(k0 + 1) * NZ_ + n];
            wr2[c][j] = pack2(w0, w1);
        }
    }

    if (tid < 64) {
        int lu = tid >> 2, c = tid & 3;          // bias per (unit, gate)
        bias_s[lu][c] = b_ih[u0 + lu + 256 * c] + b_hh[u0 + lu + 256 * c];
    }
    if (tid < 32) {
        int lu = tid >> 1, bl = tid & 1;
        int b = b0 + bl, u = u0 + lu;
        c_s[lu][bl]   = c_init[b * H_ + u];
        att_s[lu][bl] = out0[b * H_ + u];        // atten includes buf[0] = out0
    }

    auto do_gemm = [&]() {
        ull acc2[2][4];                          // [batch][gate]
        #pragma unroll
        for (int i = 0; i < 2; i++)
            #pragma unroll
            for (int c = 0; c < 4; c++) acc2[i][c] = pack2(0.f, 0.f);
        #pragma unroll
        for (int j = 0; j < 8; j++) {
            const int k0 = 32 * j + 2 * kc;
            ull h0 = *(const ull*)&h_s[0 * H_ + k0];
            ull h1 = *(const ull*)&h_s[1 * H_ + k0];
            #pragma unroll
            for (int c = 0; c < 4; c++) {
                ull wv = wr2[c][j];
                acc2[0][c] = fma2(h0, wv, acc2[0][c]);
                acc2[1][c] = fma2(h1, wv, acc2[1][c]);
            }
        }
        float acc[2][4];
        #pragma unroll
        for (int i = 0; i < 2; i++)
            #pragma unroll
            for (int c = 0; c < 4; c++) {
                float lo, hi; unpack2(acc2[i][c], lo, hi);
                acc[i][c] = lo + hi;
            }
        // butterfly-allreduce over the 16 kc lanes (stays within cs halves)
        #pragma unroll
        for (int off = 8; off >= 1; off >>= 1)
            #pragma unroll
            for (int i = 0; i < 2; i++)
                #pragma unroll
                for (int c = 0; c < 4; c++)
                    acc[i][c] += __shfl_xor_sync(0xffffffffu, acc[i][c], off);
        if (kc == 0) {
            #pragma unroll
            for (int i = 0; i < 2; i++)
                #pragma unroll
                for (int c = 0; c < 4; c++)
                    d_s[w][cs][c][i] = acc[i][c];
        }
    };

    // ---- prestep: A_0 = out0 @ Wa  (out0 excluded from h recurrence) ----
    h_s[tid] = out0[b0 * H_ + tid];
    __syncthreads();
    do_gemm();
    __syncthreads();
    if (tid < 32) {
        int lu = tid >> 1, bl = tid & 1;
        #pragma unroll
        for (int c = 0; c < 4; c++) A_s[lu][c][bl] = d_s[lu][1][c][bl];
    }
    // (t=0 gemm's d_s writes are after syncB, which waits for warp0's A_s copy)

    // ---- main sequential loop (2 syncthreads per step) ----
    for (int t = 0; t < T_; t++) {
        // warp0 prefetches this step's xz early (consumed in epilogue)
        float xzv[4];
        const int lu = (tid & 31) >> 1;
        const int bl = tid & 1;
        if (tid < 32) {
            #pragma unroll
            for (int c = 0; c < 4; c++)
                xzv[c] = __ldcg(&g_xz[(size_t)(t * NZ_ + (u0 + lu) + 256 * c) * B_ + (b0 + bl)]);
        }

        // per-warp wait: all 16 group blocks finished step t-1
        if (t > 0) {
            if (lane == 0) {
                const unsigned* ctr = &g_arr[(g * T_ + (t - 1)) * 32];
                while (acq_load(ctr) < GRPB) { }
            }
            __syncwarp();
        }

        // stage h_{t-1}: each thread one float (warp stages its own 128B slice;
        // safe: this warp passed syncC of step t-1, so all gemm reads are done)
        {
            const float* hsrc = (t == 0) ? (h_init + b0 * H_)
                                         : (&g_h[(t - 1) & 1][b0 * H_]);
            h_s[tid] = __ldcg(hsrc + tid);
        }
        __syncthreads();   // (B) full h_s visible to all warps

        do_gemm();
        __syncthreads();   // (C) d_s complete before epilogue

        if (tid < 32) {
            const int u = u0 + lu;
            const int b = b0 + bl;
            float z[4];
            #pragma unroll
            for (int c = 0; c < 4; c++) {
                float Av = A_s[lu][c][bl];
                if (t > 0) Av += d_s[lu][1][c][bl];  // A_t = A_{t-1} + h_{t-1}@Wa
                A_s[lu][c][bl] = Av;
                z[c] = xzv[c] + Av + d_s[lu][0][c][bl] + bias_s[lu][c];
            }
            float si = fsigmoid(z[0]);
            float sf = fsigmoid(z[1]);
            float tg = ftanh_(z[2]);
            float so = fsigmoid(z[3]);
            float cn = sf * c_s[lu][bl] + si * tg;
            float hn = so * ftanh_(cn);
            // publish + release FIRST (critical path), bookkeeping after
            if (t < T_ - 1) {
                __stcg(&g_h[t & 1][b * H_ + u], hn);
                __syncwarp();
                if (tid == 0) {
                    asm volatile("red.release.gpu.global.add.u32 [%0], %1;"
                                 :: "l"(&g_arr[(g * T_ + t) * 32]), "r"(1u)
                                 : "memory");
                }
            }
            c_s[lu][bl] = cn;
            if (t < T_ - 1) att_s[lu][bl] += hn;     // attens[-1] sums t<=T-2
            if (t == T_ - 2) {
                dout[3 * 4096 + b * H_ + u] = hn;    // h_prevs[-1]
                dout[4 * 4096 + b * H_ + u] = cn;    // c_prevs[-1]
            }
            if (t == T_ - 1) {
                dout[0 * 4096 + b * H_ + u] = hn;    // out_f (B,1,H)
                dout[1 * 4096 + b * H_ + u] = hn;    // h_f   (1,B,H)
                dout[2 * 4096 + b * H_ + u] = cn;    // c_f   (1,B,H)
            }
        }
    }

    if (tid < 32) {
        int lu2 = tid >> 1, bl2 = tid & 1;
        dout[5 * 4096 + (b0 + bl2) * H_ + (u0 + lu2)] = att_s[lu2][bl2];
    }
}

// ---------------------------------------------------------------------------
// inputs (metadata order): x, hidden_state, cell_state, out, Wih, Whh,
// b_ih, b_hh, W1, b1, W2, b2, W3, b3, bsize, time_step
// W1..b3 are dead (softmax over singleton axis makes weights == 1).
// ---------------------------------------------------------------------------
extern "C" void kernel_launch(void* const* d_in, const int* in_sizes, int n_in,
                              void* d_out, int out_size)
{
    const float* x       = (const float*)d_in[0];
    const float* h_init  = (const float*)d_in[1];
    const float* c_init  = (const float*)d_in[2];
    const float* out0    = (const float*)d_in[3];
    const float* Wih     = (const float*)d_in[4];
    const float* Whh     = (const float*)d_in[5];
    const float* b_ih    = (const float*)d_in[6];
    const float* b_hh    = (const float*)d_in[7];
    float* dout = (float*)d_out;

    dim3 g1(8, T_ / 2);
    xz_kernel<<<g1, 256>>>(x, Wih);
    rec_kernel<<<NBLK, 512>>>(h_init, c_init, out0, Wih, Whh, b_ih, b_hh, dout);
}